// round 2
// baseline (speedup 1.0000x reference)
#include <cuda_runtime.h>
#include <math.h>

#define NT 256
#define SMEM_FLOATS 37248
#define SMEM_BYTES (SMEM_FLOATS * 4)

// ---------------- folded-weight scratch (device globals: no allocation) ----------------
__device__ float g_A1[128 * 128];   // np_W @ im1_W[:128]
__device__ float g_A2[128 * 128];   // ep_W @ im1_W[128:]
__device__ float g_b1[128];         // np_b@im1_top + ep_b@im1_bot + im1_b

// ---------------- prep kernel: fold np/ep projections into im1 ----------------
__global__ void prep_kernel(const float* __restrict__ npW, const float* __restrict__ npb,
                            const float* __restrict__ epW, const float* __restrict__ epb,
                            const float* __restrict__ im1W, const float* __restrict__ im1b)
{
    const int i = blockIdx.x;
    const int o = threadIdx.x;
    float s1 = 0.f, s2 = 0.f;
    for (int h = 0; h < 128; ++h) {
        s1 += npW[i * 128 + h] * im1W[h * 128 + o];
        s2 += epW[i * 128 + h] * im1W[(128 + h) * 128 + o];
    }
    g_A1[i * 128 + o] = s1;
    g_A2[i * 128 + o] = s2;
    if (i == 0) {
        float sb = im1b[o];
        for (int h = 0; h < 128; ++h)
            sb += npb[h] * im1W[h * 128 + o] + epb[h] * im1W[(128 + h) * 128 + o];
        g_b1[o] = sb;
    }
}

// ---------------- params ----------------
struct Params {
    const float *src, *dst, *edge;
    const float *im2W, *im2b, *mp1W, *mp1b, *mp2W, *mp2b;
    const float *qW, *qb, *kW, *kb, *vW, *vb;
    const float *ntcW, *ntcb, *ctoW, *ctob, *outW, *outb;
    float* out;
    int B;
};

// ---------------- device helpers ----------------
__device__ __forceinline__ void load_tile(float* __restrict__ dst, const float* __restrict__ g,
                                          int rows, int tid)
{
#pragma unroll
    for (int i = 0; i < 8; ++i) {
        int f4 = tid + i * NT;            // 2048 float4 = 64x128
        int r = f4 >> 5;
        int cc = (f4 & 31) << 2;
        float4 v = make_float4(0.f, 0.f, 0.f, 0.f);
        if (r < rows) v = *(const float4*)(g + r * 128 + cc);
        *(float4*)(dst + r * 132 + cc) = v;
    }
}

__device__ __forceinline__ void init_bias(float acc[4][8], const float* __restrict__ bg, int c0)
{
    float bb[8];
#pragma unroll
    for (int j = 0; j < 8; ++j) bb[j] = __ldg(bg + c0 + j);
#pragma unroll
    for (int i = 0; i < 4; ++i)
#pragma unroll
        for (int j = 0; j < 8; ++j) acc[i][j] = bb[j];
}

__device__ __forceinline__ void init_zero(float acc[4][8])
{
#pragma unroll
    for (int i = 0; i < 4; ++i)
#pragma unroll
        for (int j = 0; j < 8; ++j) acc[i][j] = 0.f;
}

// acc += Xs[64x128] @ Wg[128x128]; weight k-tiles staged through smem WSH
__device__ __forceinline__ void gemm_acc(float acc[4][8], const float* __restrict__ Xs,
                                         const float* __restrict__ Wg, float* __restrict__ WSH,
                                         int tid, int r0, int c0)
{
    for (int kc = 0; kc < 128; kc += 32) {
#pragma unroll
        for (int i = 0; i < 4; ++i) {
            int f4 = tid + i * NT;        // 1024 float4 = 32x128
            int kk = f4 >> 5;
            int cc = (f4 & 31) << 2;
            float4 v = *(const float4*)(Wg + (kc + kk) * 128 + cc);
            *(float4*)(WSH + kk * 132 + cc) = v;
        }
        __syncthreads();
#pragma unroll 8
        for (int kk = 0; kk < 32; ++kk) {
            const float* xp = Xs + r0 * 132 + kc + kk;
            float a0 = xp[0];
            float a1 = xp[132];
            float a2 = xp[264];
            float a3 = xp[396];
            const float* wr = WSH + kk * 132 + c0;
            float4 b0 = *(const float4*)wr;
            float4 b1 = *(const float4*)(wr + 4);
            float bb[8] = {b0.x, b0.y, b0.z, b0.w, b1.x, b1.y, b1.z, b1.w};
#pragma unroll
            for (int j = 0; j < 8; ++j) {
                acc[0][j] = fmaf(a0, bb[j], acc[0][j]);
                acc[1][j] = fmaf(a1, bb[j], acc[1][j]);
                acc[2][j] = fmaf(a2, bb[j], acc[2][j]);
                acc[3][j] = fmaf(a3, bb[j], acc[3][j]);
            }
        }
        __syncthreads();
    }
}

__device__ __forceinline__ void store_act(const float acc[4][8], float* __restrict__ Out,
                                          int r0, int c0, bool relu)
{
#pragma unroll
    for (int i = 0; i < 4; ++i)
#pragma unroll
        for (int j = 0; j < 8; ++j) {
            float v = acc[i][j];
            if (relu) v = fmaxf(v, 0.f);
            Out[(r0 + i) * 132 + c0 + j] = v;
        }
}

// stage a [128x16] weight into WSH with stride 17
__device__ __forceinline__ void small_stage(float* __restrict__ WSH, const float* __restrict__ Wg,
                                            int tid)
{
    for (int e = tid; e < 2048; e += NT)
        WSH[(e >> 4) * 17 + (e & 15)] = Wg[e];
}

// Out[64x16] = (optional tanh)(Xs[64x128] @ Wsmall + b); thread t -> row t/4, 4 cols
__device__ __forceinline__ void small_compute(float* __restrict__ Out, const float* __restrict__ Xs,
                                              const float* __restrict__ WSH,
                                              const float* __restrict__ bg, int tid, bool do_tanh)
{
    const int r = tid >> 2;
    const int cb = (tid & 3) * 4;
    float a0 = __ldg(bg + cb + 0);
    float a1 = __ldg(bg + cb + 1);
    float a2 = __ldg(bg + cb + 2);
    float a3 = __ldg(bg + cb + 3);
#pragma unroll 4
    for (int k = 0; k < 128; ++k) {
        float x = Xs[r * 132 + k];
        const float* w = WSH + k * 17 + cb;
        a0 = fmaf(x, w[0], a0);
        a1 = fmaf(x, w[1], a1);
        a2 = fmaf(x, w[2], a2);
        a3 = fmaf(x, w[3], a3);
    }
    if (do_tanh) { a0 = tanhf(a0); a1 = tanhf(a1); a2 = tanhf(a2); a3 = tanhf(a3); }
    float* o = Out + r * 16 + cb;
    o[0] = a0; o[1] = a1; o[2] = a2; o[3] = a3;
}

// per-row metric + clifford products; writes IPs[r][16], SCO[r][8] = enh
__device__ __forceinline__ void clifford_row(int r, const float* __restrict__ M16s,
                                             float* __restrict__ SCs, float* __restrict__ DCs,
                                             float* __restrict__ IPs, float* __restrict__ SCO,
                                             const float* __restrict__ GSt,
                                             const float* __restrict__ WTt)
{
    float m[4][4];
#pragma unroll
    for (int a = 0; a < 4; ++a)
#pragma unroll
        for (int b = 0; b < 4; ++b) m[a][b] = M16s[r * 16 + a * 4 + b];

    float L[4][4];
#pragma unroll
    for (int a = 0; a < 4; ++a)
#pragma unroll
        for (int b = 0; b < 4; ++b) {
            if (a > b)       L[a][b] = m[a][b];
            else if (a == b) L[a][b] = log1pf(expf(m[a][a])) + 1e-6f;   // softplus (tanh-bounded input)
            else             L[a][b] = 0.f;
        }
    float met[4][4];
#pragma unroll
    for (int a = 0; a < 4; ++a)
#pragma unroll
        for (int b = 0; b < 4; ++b) {
            float s = 0.f;
#pragma unroll
            for (int c = 0; c < 4; ++c) s = fmaf(L[a][c], L[b][c], s);
            met[a][b] = s;
        }

    const int VI[4] = {1, 2, 4, 8};
#pragma unroll
    for (int t = 0; t < 2; ++t) {
        float* X = t ? DCs : SCs;
        float vin[4], vo[4];
#pragma unroll
        for (int a = 0; a < 4; ++a) vin[a] = X[r * 16 + VI[a]];
#pragma unroll
        for (int a = 0; a < 4; ++a) {
            float s = 0.f;
#pragma unroll
            for (int b = 0; b < 4; ++b) s = fmaf(met[a][b], vin[b], s);
            vo[a] = s;
        }
#pragma unroll
        for (int a = 0; a < 4; ++a) X[r * 16 + VI[a]] = vo[a];
    }

    float enh = 0.f;
    for (int k = 0; k < 16; ++k) {
        float gpk = 0.f, gprk = 0.f, opk = 0.f;
        for (int i = 0; i < 16; ++i) {
            int j = i ^ k;
            float si = SCs[r * 16 + i], sj = SCs[r * 16 + j];
            float di = DCs[r * 16 + i], dj = DCs[r * 16 + j];
            float gs = GSt[i * 16 + j];
            gpk  = fmaf(gs, si * dj, gpk);
            gprk = fmaf(gs, di * sj, gprk);
            opk  = fmaf(WTt[i * 16 + j], si * dj, opk);
        }
        IPs[r * 16 + k] = 0.5f * (gpk + gprk);
        enh += gpk + opk;
    }
#pragma unroll
    for (int h = 0; h < 8; ++h) SCO[r * 8 + h] = enh;
}

// ---------------- fused main kernel: 64 rows / CTA ----------------
__global__ __launch_bounds__(NT, 1) void fused_kernel(Params p)
{
    extern __shared__ float sm[];
    float* SB   = sm;            // 64x132 src tile (later att)
    float* BF1  = sm + 8448;     // edge -> h2 -> dst
    float* BF2  = sm + 16896;    // h1 -> h3 -> Q
    float* WSH  = sm + 25344;    // 32x132 weight staging (4224)
    float* CTOs = sm + 29568;    // cto_W 16x128
    float* M16s = sm + 31616;    // 64x16
    float* SCs  = sm + 32640;    // 64x16
    float* DCs  = sm + 33664;    // 64x16
    float* IPs  = sm + 34688;    // 64x16
    float* SCO  = sm + 35712;    // 64x8 scores
    float* W8s  = sm + 36224;    // 64x8 softmax weights
    float* GSt  = sm + 36736;    // 16x16 geo sign
    float* WTt  = sm + 36992;    // 16x16 wedge sign

    const int tid = threadIdx.x;
    const int tx = tid & 15, ty = tid >> 4;
    const int r0 = ty * 4, c0 = tx * 8;
    const int row0 = blockIdx.x * 64;
    const int rows = min(64, p.B - row0);

    // clifford sign tables (MSB-first bit convention matching reference)
    {
        int i = tid >> 4, j = tid & 15;
        float s = 1.f;
#pragma unroll
        for (int k = 0; k < 4; ++k)
            if ((j >> (3 - k)) & 1)
                if (__popc(i >> (4 - k)) & 1) s = -s;
        GSt[tid] = s;
        float w = 0.f;
        if ((i & j) == 0) {
            int inv = 0;
#pragma unroll
            for (int k = 0; k < 4; ++k)
                if ((i >> (3 - k)) & 1) inv += __popc(j & ((1 << (3 - k)) - 1));
            w = (inv & 1) ? -1.f : 1.f;
        }
        WTt[tid] = w;
    }
    for (int e = tid; e < 2048; e += NT) CTOs[e] = p.ctoW[e];

    load_tile(SB,  p.src  + (size_t)row0 * 128, rows, tid);
    load_tile(BF1, p.edge + (size_t)row0 * 128, rows, tid);

    float acc[4][8];

    // h1 = relu(src@A1 + edge@A2 + b1)  -> BF2
    init_bias(acc, g_b1, c0);
    gemm_acc(acc, SB,  g_A1, WSH, tid, r0, c0);
    gemm_acc(acc, BF1, g_A2, WSH, tid, r0, c0);
    store_act(acc, BF2, r0, c0, true);

    // h2 = relu(h1@im2W + b)  -> BF1
    init_bias(acc, p.im2b, c0);
    gemm_acc(acc, BF2, p.im2W, WSH, tid, r0, c0);
    store_act(acc, BF1, r0, c0, true);

    // h3 = relu(h2@mp1W + b)  -> BF2
    init_bias(acc, p.mp1b, c0);
    gemm_acc(acc, BF1, p.mp1W, WSH, tid, r0, c0);
    store_act(acc, BF2, r0, c0, true);

    // m16 = tanh(h3@mp2W + b)
    small_stage(WSH, p.mp2W, tid);
    __syncthreads();
    small_compute(M16s, BF2, WSH, p.mp2b, tid, true);
    // dst tile (h2 dead)
    load_tile(BF1, p.dst + (size_t)row0 * 128, rows, tid);
    __syncthreads();

    // sc = src@ntcW + b ; dc = dst@ntcW + b
    small_stage(WSH, p.ntcW, tid);
    __syncthreads();
    small_compute(SCs, SB,  WSH, p.ntcb, tid, false);
    small_compute(DCs, BF1, WSH, p.ntcb, tid, false);
    __syncthreads();

    // per-row metric + clifford products
    if (tid < 64 && tid < rows)
        clifford_row(tid, M16s, SCs, DCs, IPs, SCO, GSt, WTt);
    __syncthreads();

    // Q -> BF2 (h3 dead)
    init_bias(acc, p.qb, c0);
    gemm_acc(acc, SB, p.qW, WSH, tid, r0, c0);
    store_act(acc, BF2, r0, c0, false);

    // K GEMM with fused score epilogue: SCO += (Q.K)/4 per head
    init_bias(acc, p.kb, c0);
    gemm_acc(acc, BF1, p.kW, WSH, tid, r0, c0);
    {
        int h = c0 >> 4;                     // 8 cols lie within one head
#pragma unroll
        for (int i = 0; i < 4; ++i) {
            float pdot = 0.f;
#pragma unroll
            for (int j = 0; j < 8; ++j)
                pdot = fmaf(acc[i][j], BF2[(r0 + i) * 132 + c0 + j], pdot);
            atomicAdd(&SCO[(r0 + i) * 8 + h], 0.25f * pdot);
        }
    }
    __syncthreads();

    // softmax over 8 heads
    if (tid < 64) {
        float s0[8];
        float mx = -1e30f;
#pragma unroll
        for (int h = 0; h < 8; ++h) { s0[h] = SCO[tid * 8 + h]; mx = fmaxf(mx, s0[h]); }
        float sum = 0.f;
#pragma unroll
        for (int h = 0; h < 8; ++h) { s0[h] = expf(s0[h] - mx); sum += s0[h]; }
        float inv = 1.f / sum;
#pragma unroll
        for (int h = 0; h < 8; ++h) W8s[tid * 8 + h] = s0[h] * inv;
    }
    __syncthreads();

    // V GEMM with fused attention-weight epilogue -> att in SB (src dead)
    init_bias(acc, p.vb, c0);
    gemm_acc(acc, BF1, p.vW, WSH, tid, r0, c0);
    {
        int h = c0 >> 4;
#pragma unroll
        for (int i = 0; i < 4; ++i) {
            float w = W8s[(r0 + i) * 8 + h];
#pragma unroll
            for (int j = 0; j < 8; ++j)
                SB[(r0 + i) * 132 + c0 + j] = w * acc[i][j];
        }
    }

    // out = att@outW + out_b + ip@ctoW + cto_b
    init_zero(acc);
    gemm_acc(acc, SB, p.outW, WSH, tid, r0, c0);
#pragma unroll
    for (int i = 0; i < 4; ++i) {
        if (r0 + i >= rows) continue;
        const int row = row0 + r0 + i;
        float ip[16];
#pragma unroll
        for (int k = 0; k < 16; ++k) ip[k] = IPs[(r0 + i) * 16 + k];
#pragma unroll
        for (int j = 0; j < 8; ++j) {
            const int c = c0 + j;
            float v = acc[i][j] + __ldg(p.outb + c) + __ldg(p.ctob + c);
#pragma unroll
            for (int k = 0; k < 16; ++k) v = fmaf(ip[k], CTOs[k * 128 + c], v);
            p.out[(size_t)row * 128 + c] = v;
        }
    }
}

// ---------------- launch ----------------
extern "C" void kernel_launch(void* const* d_in, const int* in_sizes, int n_in,
                              void* d_out, int out_size)
{
    const float* src  = (const float*)d_in[0];
    const float* dst  = (const float*)d_in[1];
    const float* edge = (const float*)d_in[2];
    const float* npW  = (const float*)d_in[3];
    const float* npb  = (const float*)d_in[4];
    const float* epW  = (const float*)d_in[5];
    const float* epb  = (const float*)d_in[6];
    const float* im1W = (const float*)d_in[7];
    const float* im1b = (const float*)d_in[8];
    const float* im2W = (const float*)d_in[9];
    const float* im2b = (const float*)d_in[10];
    const float* mp1W = (const float*)d_in[11];
    const float* mp1b = (const float*)d_in[12];
    const float* mp2W = (const float*)d_in[13];
    const float* mp2b = (const float*)d_in[14];
    const float* qW   = (const float*)d_in[15];
    const float* qb   = (const float*)d_in[16];
    const float* kW   = (const float*)d_in[17];
    const float* kb   = (const float*)d_in[18];
    const float* vW   = (const float*)d_in[19];
    const float* vb   = (const float*)d_in[20];
    const float* ntcW = (const float*)d_in[21];
    const float* ntcb = (const float*)d_in[22];
    const float* ctoW = (const float*)d_in[23];
    const float* ctob = (const float*)d_in[24];
    const float* outW = (const float*)d_in[25];
    const float* outb = (const float*)d_in[26];
    // d_in[27] = edge_indices: unused by the reference computation.

    const int B = in_sizes[0] / 128;

    cudaFuncSetAttribute(fused_kernel, cudaFuncAttributeMaxDynamicSharedMemorySize, SMEM_BYTES);

    prep_kernel<<<128, 128>>>(npW, npb, epW, epb, im1W, im1b);

    Params p;
    p.src = src; p.dst = dst; p.edge = edge;
    p.im2W = im2W; p.im2b = im2b; p.mp1W = mp1W; p.mp1b = mp1b;
    p.mp2W = mp2W; p.mp2b = mp2b;
    p.qW = qW; p.qb = qb; p.kW = kW; p.kb = kb; p.vW = vW; p.vb = vb;
    p.ntcW = ntcW; p.ntcb = ntcb; p.ctoW = ctoW; p.ctob = ctob;
    p.outW = outW; p.outb = outb;
    p.out = (float*)d_out; p.B = B;

    fused_kernel<<<(B + 63) / 64, NT, SMEM_BYTES>>>(p);
}

// round 3
// speedup vs baseline: 1.0475x; 1.0475x over previous
#include <cuda_runtime.h>
#include <math.h>

#define NT 256
#define PAD 68
#define XTSZ (128 * PAD)           // 8704 floats per activation buffer
#define SMEM_FLOATS 50176
#define SMEM_BYTES (SMEM_FLOATS * 4)

// ---------------- folded-weight scratch ----------------
__device__ float g_A1[128 * 128];
__device__ float g_A2[128 * 128];
__device__ float g_b1[128];

__global__ void prep_kernel(const float* __restrict__ npW, const float* __restrict__ npb,
                            const float* __restrict__ epW, const float* __restrict__ epb,
                            const float* __restrict__ im1W, const float* __restrict__ im1b)
{
    const int i = blockIdx.x;
    const int o = threadIdx.x;
    float s1 = 0.f, s2 = 0.f;
    for (int h = 0; h < 128; ++h) {
        s1 += npW[i * 128 + h] * im1W[h * 128 + o];
        s2 += epW[i * 128 + h] * im1W[(128 + h) * 128 + o];
    }
    g_A1[i * 128 + o] = s1;
    g_A2[i * 128 + o] = s2;
    if (i == 0) {
        float sb = im1b[o];
        for (int h = 0; h < 128; ++h)
            sb += npb[h] * im1W[h * 128 + o] + epb[h] * im1W[(128 + h) * 128 + o];
        g_b1[o] = sb;
    }
}

struct Params {
    const float *src, *dst, *edge;
    const float *im2W, *im2b, *mp1W, *mp1b, *mp2W, *mp2b;
    const float *qW, *qb, *kW, *kb, *vW, *vb;
    const float *ntcW, *ntcb, *ctoW, *ctob, *outW, *outb;
    float* out;
    int B;
};

// ---------------- f32x2 helpers ----------------
union F2U { float2 f; unsigned long long u; };

__device__ __forceinline__ unsigned long long dup2(float x) {
    F2U u; u.f.x = x; u.f.y = x; return u.u;
}

#define FMA2(d, a, b) asm("fma.rn.f32x2 %0, %1, %2, %0;" : "+l"(d) : "l"(a), "l"(b))

// ---------------- global -> transposed smem tile ----------------
__device__ __forceinline__ void load_tile(float* __restrict__ XT, const float* __restrict__ g,
                                          int rows, int tid)
{
#pragma unroll
    for (int i = 0; i < 8; ++i) {
        int f4 = tid + i * NT;                 // 2048 float4 = 64x128
        int r = f4 >> 5;
        int cc = (f4 & 31) << 2;
        float4 v = make_float4(0.f, 0.f, 0.f, 0.f);
        if (r < rows) v = *(const float4*)(g + r * 128 + cc);
        XT[(cc + 0) * PAD + r] = v.x;
        XT[(cc + 1) * PAD + r] = v.y;
        XT[(cc + 2) * PAD + r] = v.z;
        XT[(cc + 3) * PAD + r] = v.w;
    }
}

// ---------------- weight staging (duplicated f32x2 pairs), double-buffered ----------------
__device__ __forceinline__ void stg_store(unsigned long long* __restrict__ buf,
                                          const float4* __restrict__ pv, int tid)
{
#pragma unroll
    for (int i = 0; i < 4; ++i) {
        int e = tid + i * NT;                  // 1024 float4 = 32x128 chunk
        int k = e >> 5;
        int c4 = (e & 31) << 2;
        float4 v = pv[i];
        ulonglong2 d0; d0.x = dup2(v.x); d0.y = dup2(v.y);
        ulonglong2 d1; d1.x = dup2(v.z); d1.y = dup2(v.w);
        *(ulonglong2*)(buf + k * 128 + c4)     = d0;
        *(ulonglong2*)(buf + k * 128 + c4 + 2) = d1;
    }
}

__device__ __forceinline__ void init_bias2(unsigned long long acc[8][2],
                                           const float* __restrict__ bg, int cl2)
{
    unsigned long long b0 = dup2(__ldg(bg + cl2));
    unsigned long long b1 = dup2(__ldg(bg + cl2 + 1));
#pragma unroll
    for (int p = 0; p < 8; ++p) { acc[p][0] = b0; acc[p][1] = b1; }
}

__device__ __forceinline__ void init_zero2(unsigned long long acc[8][2])
{
#pragma unroll
    for (int p = 0; p < 8; ++p) { acc[p][0] = 0ull; acc[p][1] = 0ull; }
}

// acc += XT[64x128]^T-layout @ Wg[128x128] ; packed rows (f32x2), dup'd B
__device__ __forceinline__ void gemm_acc2(unsigned long long acc[8][2],
                                          const float* __restrict__ XT,
                                          const float* __restrict__ Wg,
                                          unsigned long long* __restrict__ WSH2,
                                          int tid, int rg16, int cl2)
{
    float4 pv[4];
#pragma unroll
    for (int i = 0; i < 4; ++i)
        pv[i] = *(const float4*)(Wg + (tid + i * NT) * 4);
    stg_store(WSH2, pv, tid);
    __syncthreads();

#pragma unroll
    for (int ch = 0; ch < 4; ++ch) {
        if (ch < 3) {
#pragma unroll
            for (int i = 0; i < 4; ++i)
                pv[i] = *(const float4*)(Wg + (ch + 1) * 32 * 128 + (tid + i * NT) * 4);
        }
        const unsigned long long* buf = WSH2 + (ch & 1) * 4096;
        const float* xb = XT + ch * 32 * PAD + rg16;
#pragma unroll 4
        for (int kk = 0; kk < 32; ++kk) {
            const float* xk = xb + kk * PAD;
            ulonglong2 a0 = *(const ulonglong2*)(xk);
            ulonglong2 a1 = *(const ulonglong2*)(xk + 4);
            ulonglong2 a2 = *(const ulonglong2*)(xk + 8);
            ulonglong2 a3 = *(const ulonglong2*)(xk + 12);
            ulonglong2 b  = *(const ulonglong2*)(buf + kk * 128 + cl2);
            FMA2(acc[0][0], a0.x, b.x); FMA2(acc[0][1], a0.x, b.y);
            FMA2(acc[1][0], a0.y, b.x); FMA2(acc[1][1], a0.y, b.y);
            FMA2(acc[2][0], a1.x, b.x); FMA2(acc[2][1], a1.x, b.y);
            FMA2(acc[3][0], a1.y, b.x); FMA2(acc[3][1], a1.y, b.y);
            FMA2(acc[4][0], a2.x, b.x); FMA2(acc[4][1], a2.x, b.y);
            FMA2(acc[5][0], a2.y, b.x); FMA2(acc[5][1], a2.y, b.y);
            FMA2(acc[6][0], a3.x, b.x); FMA2(acc[6][1], a3.x, b.y);
            FMA2(acc[7][0], a3.y, b.x); FMA2(acc[7][1], a3.y, b.y);
        }
        if (ch < 3) {
            stg_store(WSH2 + ((ch + 1) & 1) * 4096, pv, tid);
            __syncthreads();
        }
    }
    __syncthreads();
}

__device__ __forceinline__ void store_act2(const unsigned long long acc[8][2],
                                           float* __restrict__ Out, int rg16, int cl2, bool relu)
{
#pragma unroll
    for (int p = 0; p < 8; ++p) {
        int rb = rg16 + 2 * p;
#pragma unroll
        for (int c = 0; c < 2; ++c) {
            F2U u; u.u = acc[p][c];
            float2 f = u.f;
            if (relu) { f.x = fmaxf(f.x, 0.f); f.y = fmaxf(f.y, 0.f); }
            *(float2*)(Out + (cl2 + c) * PAD + rb) = f;
        }
    }
}

// ---------------- small 128->16 GEMMs ----------------
__device__ __forceinline__ void small_stage(float* __restrict__ WS, const float* __restrict__ Wg,
                                            int tid)
{
    for (int e = tid; e < 2048; e += NT)
        WS[(e >> 4) * 17 + (e & 15)] = Wg[e];
}

__device__ __forceinline__ void small_compute(float* __restrict__ Out, const float* __restrict__ XT,
                                              const float* __restrict__ WS,
                                              const float* __restrict__ bg, int tid, bool do_tanh)
{
    const int r = tid >> 2;
    const int cb = (tid & 3) * 4;
    float a0 = __ldg(bg + cb + 0);
    float a1 = __ldg(bg + cb + 1);
    float a2 = __ldg(bg + cb + 2);
    float a3 = __ldg(bg + cb + 3);
#pragma unroll 4
    for (int k = 0; k < 128; ++k) {
        float x = XT[k * PAD + r];
        const float* w = WS + k * 17 + cb;
        a0 = fmaf(x, w[0], a0);
        a1 = fmaf(x, w[1], a1);
        a2 = fmaf(x, w[2], a2);
        a3 = fmaf(x, w[3], a3);
    }
    if (do_tanh) { a0 = tanhf(a0); a1 = tanhf(a1); a2 = tanhf(a2); a3 = tanhf(a3); }
    float* o = Out + r * 16 + cb;
    o[0] = a0; o[1] = a1; o[2] = a2; o[3] = a3;
}

// ---------------- per-row metric + clifford products ----------------
__device__ __forceinline__ void clifford_row(int r, const float* __restrict__ M16s,
                                             float* __restrict__ SCs, float* __restrict__ DCs,
                                             float* __restrict__ IPs, float* __restrict__ SCO,
                                             const float* __restrict__ GSt,
                                             const float* __restrict__ WTt)
{
    float m[4][4];
#pragma unroll
    for (int a = 0; a < 4; ++a)
#pragma unroll
        for (int b = 0; b < 4; ++b) m[a][b] = M16s[r * 16 + a * 4 + b];

    float L[4][4];
#pragma unroll
    for (int a = 0; a < 4; ++a)
#pragma unroll
        for (int b = 0; b < 4; ++b) {
            if (a > b)       L[a][b] = m[a][b];
            else if (a == b) L[a][b] = log1pf(expf(m[a][a])) + 1e-6f;
            else             L[a][b] = 0.f;
        }
    float met[4][4];
#pragma unroll
    for (int a = 0; a < 4; ++a)
#pragma unroll
        for (int b = 0; b < 4; ++b) {
            float s = 0.f;
#pragma unroll
            for (int c = 0; c < 4; ++c) s = fmaf(L[a][c], L[b][c], s);
            met[a][b] = s;
        }

    const int VI[4] = {1, 2, 4, 8};
#pragma unroll
    for (int t = 0; t < 2; ++t) {
        float* X = t ? DCs : SCs;
        float vin[4], vo[4];
#pragma unroll
        for (int a = 0; a < 4; ++a) vin[a] = X[r * 16 + VI[a]];
#pragma unroll
        for (int a = 0; a < 4; ++a) {
            float s = 0.f;
#pragma unroll
            for (int b = 0; b < 4; ++b) s = fmaf(met[a][b], vin[b], s);
            vo[a] = s;
        }
#pragma unroll
        for (int a = 0; a < 4; ++a) X[r * 16 + VI[a]] = vo[a];
    }

    float enh = 0.f;
    for (int k = 0; k < 16; ++k) {
        float gpk = 0.f, gprk = 0.f, opk = 0.f;
        for (int i = 0; i < 16; ++i) {
            int j = i ^ k;
            float si = SCs[r * 16 + i], sj = SCs[r * 16 + j];
            float di = DCs[r * 16 + i], dj = DCs[r * 16 + j];
            float gs = GSt[i * 16 + j];
            gpk  = fmaf(gs, si * dj, gpk);
            gprk = fmaf(gs, di * sj, gprk);
            opk  = fmaf(WTt[i * 16 + j], si * dj, opk);
        }
        IPs[r * 16 + k] = 0.5f * (gpk + gprk);
        enh += gpk + opk;
    }
#pragma unroll
    for (int h = 0; h < 8; ++h) SCO[r * 8 + h] = enh;
}

// ---------------- fused kernel ----------------
__global__ __launch_bounds__(NT) void fused_kernel(Params p)
{
    extern __shared__ float sm[];
    float* XT_S = sm;                       // src -> att
    float* XT_E = sm + XTSZ;                // edge -> h2 -> dst
    float* XT_B = sm + 2 * XTSZ;            // h1 -> h3 -> Q
    unsigned long long* WSH2 = (unsigned long long*)(sm + 26112);   // 2 x 4096 ull
    float* WS   = (float*)WSH2;             // reuse for small-W staging
    float* CTOs = sm + 42496;               // 16x128
    float* M16s = sm + 44544;               // 64x16
    float* SCs  = sm + 45568;
    float* DCs  = sm + 46592;
    float* IPs  = sm + 47616;
    float* SCO  = sm + 48640;               // 64x8
    float* W8s  = sm + 49152;               // 64x8
    float* GSt  = sm + 49664;               // 16x16
    float* WTt  = sm + 49920;               // 16x16

    const int tid = threadIdx.x;
    const int rg16 = (tid >> 6) * 16;       // 4 row groups of 16 rows
    const int cl = tid & 63;                // 64 col-pairs
    const int cl2 = cl * 2;
    const int row0 = blockIdx.x * 64;
    const int rows = min(64, p.B - row0);

    // sign tables (MSB-first convention)
    {
        int i = tid >> 4, j = tid & 15;
        if (tid < 256) {
            float s = 1.f;
#pragma unroll
            for (int k = 0; k < 4; ++k)
                if ((j >> (3 - k)) & 1)
                    if (__popc(i >> (4 - k)) & 1) s = -s;
            GSt[tid] = s;
            float w = 0.f;
            if ((i & j) == 0) {
                int inv = 0;
#pragma unroll
                for (int k = 0; k < 4; ++k)
                    if ((i >> (3 - k)) & 1) inv += __popc(j & ((1 << (3 - k)) - 1));
                w = (inv & 1) ? -1.f : 1.f;
            }
            WTt[tid] = w;
        }
    }
    for (int e = tid; e < 2048; e += NT) CTOs[e] = p.ctoW[e];
    for (int e = tid; e < 512; e += NT) SCO[e] = 0.f;

    load_tile(XT_S, p.src  + (size_t)row0 * 128, rows, tid);
    load_tile(XT_E, p.edge + (size_t)row0 * 128, rows, tid);

    unsigned long long acc[8][2];

    // h1 = relu(src@A1 + edge@A2 + b1) -> XT_B
    init_bias2(acc, g_b1, cl2);
    gemm_acc2(acc, XT_S, g_A1, WSH2, tid, rg16, cl2);
    gemm_acc2(acc, XT_E, g_A2, WSH2, tid, rg16, cl2);
    store_act2(acc, XT_B, rg16, cl2, true);

    // h2 = relu(h1@im2W + b) -> XT_E
    init_bias2(acc, p.im2b, cl2);
    gemm_acc2(acc, XT_B, p.im2W, WSH2, tid, rg16, cl2);
    store_act2(acc, XT_E, rg16, cl2, true);

    // h3 = relu(h2@mp1W + b) -> XT_B
    init_bias2(acc, p.mp1b, cl2);
    gemm_acc2(acc, XT_E, p.mp1W, WSH2, tid, rg16, cl2);
    store_act2(acc, XT_B, rg16, cl2, true);
    __syncthreads();

    // m16 = tanh(h3@mp2W + b)
    small_stage(WS, p.mp2W, tid);
    __syncthreads();
    small_compute(M16s, XT_B, WS, p.mp2b, tid, true);
    // dst -> XT_E (h2 dead)
    load_tile(XT_E, p.dst + (size_t)row0 * 128, rows, tid);
    __syncthreads();

    // sc = src@ntcW + b ; dc = dst@ntcW + b
    small_stage(WS, p.ntcW, tid);
    __syncthreads();
    small_compute(SCs, XT_S, WS, p.ntcb, tid, false);
    small_compute(DCs, XT_E, WS, p.ntcb, tid, false);
    __syncthreads();

    if (tid < 64 && tid < rows)
        clifford_row(tid, M16s, SCs, DCs, IPs, SCO, GSt, WTt);
    __syncthreads();

    // Q = src@qW + b -> XT_B (h3 dead)
    init_bias2(acc, p.qb, cl2);
    gemm_acc2(acc, XT_S, p.qW, WSH2, tid, rg16, cl2);
    store_act2(acc, XT_B, rg16, cl2, false);

    // K GEMM with fused Q.K score epilogue
    init_bias2(acc, p.kb, cl2);
    gemm_acc2(acc, XT_E, p.kW, WSH2, tid, rg16, cl2);
    {
        const int h = cl >> 3;               // 16 cols per head, 2 cols/thread
#pragma unroll
        for (int pp = 0; pp < 8; ++pp) {
            int rb = rg16 + 2 * pp;
            float2 q0 = *(const float2*)(XT_B + (cl2 + 0) * PAD + rb);
            float2 q1 = *(const float2*)(XT_B + (cl2 + 1) * PAD + rb);
            F2U k0; k0.u = acc[pp][0];
            F2U k1; k1.u = acc[pp][1];
            float de = fmaf(k0.f.x, q0.x, k1.f.x * q1.x);
            float do_ = fmaf(k0.f.y, q0.y, k1.f.y * q1.y);
            atomicAdd(&SCO[rb * 8 + h], 0.25f * de);
            atomicAdd(&SCO[(rb + 1) * 8 + h], 0.25f * do_);
        }
    }
    __syncthreads();

    // softmax over 8 heads
    if (tid < 64) {
        float s0[8];
        float mx = -1e30f;
#pragma unroll
        for (int h = 0; h < 8; ++h) { s0[h] = SCO[tid * 8 + h]; mx = fmaxf(mx, s0[h]); }
        float sum = 0.f;
#pragma unroll
        for (int h = 0; h < 8; ++h) { s0[h] = expf(s0[h] - mx); sum += s0[h]; }
        float inv = 1.f / sum;
#pragma unroll
        for (int h = 0; h < 8; ++h) W8s[tid * 8 + h] = s0[h] * inv;
    }
    __syncthreads();

    // V GEMM with fused attention weights -> att in XT_S (src dead)
    init_bias2(acc, p.vb, cl2);
    gemm_acc2(acc, XT_E, p.vW, WSH2, tid, rg16, cl2);
    {
        const int h = cl >> 3;
#pragma unroll
        for (int pp = 0; pp < 8; ++pp) {
            int rb = rg16 + 2 * pp;
            float w0 = W8s[rb * 8 + h];
            float w1 = W8s[(rb + 1) * 8 + h];
#pragma unroll
            for (int c = 0; c < 2; ++c) {
                F2U u; u.u = acc[pp][c];
                float2 o; o.x = u.f.x * w0; o.y = u.f.y * w1;
                *(float2*)(XT_S + (cl2 + c) * PAD + rb) = o;
            }
        }
    }
    __syncthreads();

    // out = att@outW + out_b + ip@ctoW + cto_b
    init_zero2(acc);
    gemm_acc2(acc, XT_S, p.outW, WSH2, tid, rg16, cl2);
    {
        float bc[2], ct[2][16];
#pragma unroll
        for (int c = 0; c < 2; ++c) {
            bc[c] = __ldg(p.outb + cl2 + c) + __ldg(p.ctob + cl2 + c);
#pragma unroll
            for (int k = 0; k < 16; ++k) ct[c][k] = CTOs[k * 128 + cl2 + c];
        }
#pragma unroll
        for (int pp = 0; pp < 8; ++pp) {
            int rb = rg16 + 2 * pp;
            float ip0[16], ip1[16];
#pragma unroll
            for (int k = 0; k < 16; ++k) {
                ip0[k] = IPs[rb * 16 + k];
                ip1[k] = IPs[(rb + 1) * 16 + k];
            }
#pragma unroll
            for (int c = 0; c < 2; ++c) {
                F2U u; u.u = acc[pp][c];
                float v0 = u.f.x + bc[c];
                float v1 = u.f.y + bc[c];
#pragma unroll
                for (int k = 0; k < 16; ++k) {
                    v0 = fmaf(ip0[k], ct[c][k], v0);
                    v1 = fmaf(ip1[k], ct[c][k], v1);
                }
                if (rb < rows)     p.out[(size_t)(row0 + rb) * 128 + cl2 + c] = v0;
                if (rb + 1 < rows) p.out[(size_t)(row0 + rb + 1) * 128 + cl2 + c] = v1;
            }
        }
    }
}

// ---------------- launch ----------------
extern "C" void kernel_launch(void* const* d_in, const int* in_sizes, int n_in,
                              void* d_out, int out_size)
{
    const float* src  = (const float*)d_in[0];
    const float* dst  = (const float*)d_in[1];
    const float* edge = (const float*)d_in[2];
    const float* npW  = (const float*)d_in[3];
    const float* npb  = (const float*)d_in[4];
    const float* epW  = (const float*)d_in[5];
    const float* epb  = (const float*)d_in[6];
    const float* im1W = (const float*)d_in[7];
    const float* im1b = (const float*)d_in[8];
    const float* im2W = (const float*)d_in[9];
    const float* im2b = (const float*)d_in[10];
    const float* mp1W = (const float*)d_in[11];
    const float* mp1b = (const float*)d_in[12];
    const float* mp2W = (const float*)d_in[13];
    const float* mp2b = (const float*)d_in[14];
    const float* qW   = (const float*)d_in[15];
    const float* qb   = (const float*)d_in[16];
    const float* kW   = (const float*)d_in[17];
    const float* kb   = (const float*)d_in[18];
    const float* vW   = (const float*)d_in[19];
    const float* vb   = (const float*)d_in[20];
    const float* ntcW = (const float*)d_in[21];
    const float* ntcb = (const float*)d_in[22];
    const float* ctoW = (const float*)d_in[23];
    const float* ctob = (const float*)d_in[24];
    const float* outW = (const float*)d_in[25];
    const float* outb = (const float*)d_in[26];

    const int B = in_sizes[0] / 128;

    cudaFuncSetAttribute(fused_kernel, cudaFuncAttributeMaxDynamicSharedMemorySize, SMEM_BYTES);

    prep_kernel<<<128, 128>>>(npW, npb, epW, epb, im1W, im1b);

    Params p;
    p.src = src; p.dst = dst; p.edge = edge;
    p.im2W = im2W; p.im2b = im2b; p.mp1W = mp1W; p.mp1b = mp1b;
    p.mp2W = mp2W; p.mp2b = mp2b;
    p.qW = qW; p.qb = qb; p.kW = kW; p.kb = kb; p.vW = vW; p.vb = vb;
    p.ntcW = ntcW; p.ntcb = ntcb; p.ctoW = ctoW; p.ctob = ctob;
    p.outW = outW; p.outb = outb;
    p.out = (float*)d_out; p.B = B;

    fused_kernel<<<(B + 63) / 64, NT, SMEM_BYTES>>>(p);
}